// round 3
// baseline (speedup 1.0000x reference)
#include <cuda_runtime.h>
#include <cstdint>

// DVBundle, cluster-split TMA-pipelined persistent kernel.
//
// w [4096, 8192, 4] f32 (float4 per (n,i)), x [8192,4], v/r [4096].
// Output: [v_new (N) | r_new (N) | w_new (N*8192*4)]
//
// Grid = 148 CTAs = 74 clusters of 2. Cluster handles neurons n = cid, cid+74, ...
// Rank r covers inputs [r*4096, r*4096+4096): 64KB w tile per CTA per neuron.
// x slice lives permanently in registers. w tiles stream into a 3-deep smem
// ring via cp.async.bulk + mbarrier (bulk DRAM reads, fully decoupled from
// compute). Partial I exchanged across the pair via DSMEM + cluster.sync.

#define NI        8192
#define HALF      4096
#define THREADS   1024
#define VPTH      4            // float4 per thread per half-row
#define CLUSTERS  74
#define NBUF      3
#define HALF_BYTES (HALF * 16)

#define OFF_RED    (NBUF * HALF_BYTES)          // red[0..31] partials, red[32] own total
#define OFF_PEER   (OFF_RED + 34 * 16)          // 2 parity slots for peer partial
#define OFF_MBAR   (OFF_PEER + 2 * 16)          // 3 x u64 mbarriers
#define SMEM_BYTES (OFF_MBAR + 64)

__device__ __forceinline__ void mbar_wait_parity(uint32_t mbar, uint32_t parity)
{
    uint32_t done;
    asm volatile(
        "{\n\t.reg .pred p;\n\t"
        "mbarrier.try_wait.parity.acquire.cta.shared::cta.b64 p, [%1], %2;\n\t"
        "selp.b32 %0, 1, 0, p;\n\t}"
        : "=r"(done) : "r"(mbar), "r"(parity) : "memory");
    if (!done) {
        asm volatile(
            "{\n\t.reg .pred P1;\n\t"
            "WL_%=:\n\t"
            "mbarrier.try_wait.parity.acquire.cta.shared::cta.b64 P1, [%0], %1, 0x989680;\n\t"
            "@P1 bra.uni WD_%=;\n\t"
            "bra.uni WL_%=;\n\t"
            "WD_%=:\n\t}"
            :: "r"(mbar), "r"(parity) : "memory");
    }
}

__global__ __launch_bounds__(THREADS, 1) __cluster_dims__(2, 1, 1)
void dvbundle_tma(const float4* __restrict__ w,
                  const float4* __restrict__ x,
                  const float*  __restrict__ v,
                  const float*  __restrict__ r,
                  float*        __restrict__ v_out,
                  float*        __restrict__ r_out,
                  float4*       __restrict__ w_out,
                  int n_neurons)
{
    extern __shared__ char smem[];
    float4* red       = (float4*)(smem + OFF_RED);
    float4* peer_slot = (float4*)(smem + OFF_PEER);

    const int tid  = threadIdx.x;
    const int warp = tid >> 5;
    const int lane = tid & 31;

    uint32_t rank;
    asm("mov.u32 %0, %%cluster_ctarank;" : "=r"(rank));
    const int cid = blockIdx.x >> 1;

    const uint32_t smem_base = (uint32_t)__cvta_generic_to_shared(smem);
    const uint32_t mbar_base = smem_base + OFF_MBAR;

    // ---- x slice: permanent registers ----
    float4 xv[VPTH];
#pragma unroll
    for (int j = 0; j < VPTH; ++j)
        xv[j] = x[rank * HALF + tid + j * THREADS];

    if (tid == 0) {
#pragma unroll
        for (int b = 0; b < NBUF; ++b)
            asm volatile("mbarrier.init.shared.b64 [%0], %1;"
                         :: "r"(mbar_base + 8u * b), "r"(1u) : "memory");
    }
    __syncthreads();

    const float4* wsrc_base = w + (size_t)rank * HALF;   // + (size_t)n * NI

    // ---- Prologue: fill the ring (rows cid, cid+74, cid+148) ----
    if (tid == 0) {
        int nn = cid;
#pragma unroll
        for (int b = 0; b < NBUF; ++b, nn += CLUSTERS) {
            if (nn < n_neurons) {
                const uint32_t mb = mbar_base + 8u * b;
                asm volatile("mbarrier.arrive.expect_tx.shared.b64 _, [%0], %1;"
                             :: "r"(mb), "r"((uint32_t)HALF_BYTES) : "memory");
                const void* src = (const void*)(wsrc_base + (size_t)nn * NI);
                asm volatile(
                    "cp.async.bulk.shared::cluster.global.mbarrier::complete_tx::bytes "
                    "[%0], [%1], %2, [%3];"
                    :: "r"(smem_base + (uint32_t)(b * HALF_BYTES)),
                       "l"(src), "r"((uint32_t)HALF_BYTES), "r"(mb) : "memory");
            }
        }
    }

    int it = 0;
    for (int n = cid; n < n_neurons; n += CLUSTERS, ++it) {
        const int      b      = it % NBUF;
        const uint32_t parity = (uint32_t)(it / NBUF) & 1u;
        const uint32_t mb     = mbar_base + 8u * b;

        mbar_wait_parity(mb, parity);

        // ---- Pass 1: smem tile -> regs, FMA with resident x ----
        const float4* wb = (const float4*)(smem + b * HALF_BYTES);
        float4 wv[VPTH];
        float ax = 0.f, ay = 0.f, az = 0.f, aw = 0.f;
#pragma unroll
        for (int j = 0; j < VPTH; ++j) {
            wv[j] = wb[tid + j * THREADS];
            ax = fmaf(wv[j].x, xv[j].x, ax);
            ay = fmaf(wv[j].y, xv[j].y, ay);
            az = fmaf(wv[j].z, xv[j].z, az);
            aw = fmaf(wv[j].w, xv[j].w, aw);
        }

#pragma unroll
        for (int o = 16; o > 0; o >>= 1) {
            ax += __shfl_xor_sync(0xffffffffu, ax, o);
            ay += __shfl_xor_sync(0xffffffffu, ay, o);
            az += __shfl_xor_sync(0xffffffffu, az, o);
            aw += __shfl_xor_sync(0xffffffffu, aw, o);
        }
        if (lane == 0) red[warp] = make_float4(ax, ay, az, aw);
        __syncthreads();   // all threads done reading wbuf[b]

        // ---- Refill freed buffer immediately (DRAM keeps streaming) ----
        if (tid == 0) {
            const int nn = n + NBUF * CLUSTERS;
            if (nn < n_neurons) {
                asm volatile("mbarrier.arrive.expect_tx.shared.b64 _, [%0], %1;"
                             :: "r"(mb), "r"((uint32_t)HALF_BYTES) : "memory");
                const void* src = (const void*)(wsrc_base + (size_t)nn * NI);
                asm volatile(
                    "cp.async.bulk.shared::cluster.global.mbarrier::complete_tx::bytes "
                    "[%0], [%1], %2, [%3];"
                    :: "r"(smem_base + (uint32_t)(b * HALF_BYTES)),
                       "l"(src), "r"((uint32_t)HALF_BYTES), "r"(mb) : "memory");
            }
        }

        // ---- Second-stage reduce + DSMEM push of partial to peer ----
        if (warp == 0) {
            float4 t = red[lane];
            float bx = t.x, by = t.y, bz = t.z, bw = t.w;
#pragma unroll
            for (int o = 16; o > 0; o >>= 1) {
                bx += __shfl_xor_sync(0xffffffffu, bx, o);
                by += __shfl_xor_sync(0xffffffffu, by, o);
                bz += __shfl_xor_sync(0xffffffffu, bz, o);
                bw += __shfl_xor_sync(0xffffffffu, bw, o);
            }
            if (lane == 0) {
                red[32] = make_float4(bx, by, bz, bw);
                const uint32_t local =
                    smem_base + (uint32_t)OFF_PEER + (uint32_t)((it & 1) * 16);
                uint32_t remote;
                asm("mapa.shared::cluster.u32 %0, %1, %2;"
                    : "=r"(remote) : "r"(local), "r"(rank ^ 1u));
                asm volatile("st.shared::cluster.b32 [%0],      %1;" :: "r"(remote),       "r"(__float_as_uint(bx)) : "memory");
                asm volatile("st.shared::cluster.b32 [%0+4],   %1;" :: "r"(remote),       "r"(__float_as_uint(by)) : "memory");
                asm volatile("st.shared::cluster.b32 [%0+8],   %1;" :: "r"(remote),       "r"(__float_as_uint(bz)) : "memory");
                asm volatile("st.shared::cluster.b32 [%0+12],  %1;" :: "r"(remote),       "r"(__float_as_uint(bw)) : "memory");
            }
        }

        asm volatile("barrier.cluster.arrive.aligned;" ::: "memory");
        asm volatile("barrier.cluster.wait.aligned;"   ::: "memory");

        const float4 Io = red[32];
        const float4 Ip = peer_slot[it & 1];
        const float Ix = Io.x + Ip.x;
        const float Iy = Io.y + Ip.y;
        const float Iz = Io.z + Ip.z;
        const float Iw = Io.w + Ip.w;

        // ---- Scalar neuron update ----
        const float vn   = v[n];
        const float rn   = r[n];
        const float S    = Ix - Iy + Iz - Iw;
        const float dv   = (S - vn) * 0.05f;            // DT/TAU_V
        const float th   = tanhf(vn);
        const float actd = (vn > 0.f) ? (1.f - th * th) : 0.f;
        const float reg  = rn * actd * dv * 0.02f;      // / TAU_W

        if (rank == 0 && tid == 0) {
            v_out[n] = vn + dv;
            r_out[n] = (vn > 0.f) ? th : 0.f;
        }

        // ---- Pass 2: pure register math + direct STG ----
        float4* wdst = w_out + (size_t)n * NI + (size_t)rank * HALF;
#pragma unroll
        for (int j = 0; j < VPTH; ++j) {
            const float4 wj = wv[j];
            float4 o;
            o.x = fmaf(reg, fmaf(-wj.x, Ix, 0.5f * xv[j].x), wj.x);
            o.y = fmaf(reg, fmaf(-wj.y, Iy, 0.5f * xv[j].y), wj.y);
            o.z = fmaf(reg, fmaf(-wj.z, Iz, 0.5f * xv[j].z), wj.z);
            o.w = fmaf(reg, fmaf(-wj.w, Iw, 0.5f * xv[j].w), wj.w);
            wdst[tid + j * THREADS] = o;
        }
    }
}

extern "C" void kernel_launch(void* const* d_in, const int* in_sizes, int n_in,
                              void* d_out, int out_size)
{
    const float4* w = (const float4*)d_in[0];
    const float4* x = (const float4*)d_in[1];
    const float*  v = (const float*)d_in[2];
    const float*  r = (const float*)d_in[3];

    const int N = in_sizes[2];                 // 4096 neurons

    float*  out   = (float*)d_out;
    float*  v_out = out;
    float*  r_out = out + N;
    float4* w_out = (float4*)(out + 2 * (size_t)N);

    cudaFuncSetAttribute(dvbundle_tma,
                         cudaFuncAttributeMaxDynamicSharedMemorySize,
                         SMEM_BYTES);

    dvbundle_tma<<<2 * CLUSTERS, THREADS, SMEM_BYTES>>>(w, x, v, r,
                                                        v_out, r_out, w_out, N);
}

// round 4
// speedup vs baseline: 1.5382x; 1.5382x over previous
#include <cuda_runtime.h>
#include <cstdint>

// DVBundle: intra-CTA TMA-ring persistent kernel (no clusters).
//
// w [4096, 8192, 4] f32 = 8192 float4 per neuron row (128KB).
// x [8192,4] -> 8192 float4 (128KB, cached in smem once).
// Output: [v_new (N) | r_new (N) | w_new (N*8192*4)]
//
// Grid = 148 persistent CTAs, 1024 threads. Each CTA loops neurons
// n = bid, bid+148, ... Row streamed as 4 tiles of 32KB via cp.async.bulk
// into a 3-deep smem ring; tiles LDS'd into wv[8] regs (held through the
// update so w is read from DRAM exactly once). Single reduce barrier with
// redundant per-warp broadcast reduce. Per-tile barrier + immediate refill
// keeps the TMA engine streaming through the reduction and store phases.

#define NI        8192
#define THREADS   1024
#define GRID      148
#define TILE_F4   2048               // 32KB tile = 2048 float4
#define TILE_B    32768
#define NBUF      3

#define OFF_X     0
#define OFF_RING  (NI * 16)                      // 131072
#define OFF_RED   (OFF_RING + NBUF * TILE_B)     // 229376
#define OFF_MBAR  (OFF_RED + 33 * 16)            // 229904 (8-aligned)
#define SMEM_B    (OFF_MBAR + NBUF * 8)          // 229928

__device__ __forceinline__ void mbar_wait_parity(uint32_t mbar, uint32_t parity)
{
    uint32_t done;
    asm volatile(
        "{\n\t.reg .pred p;\n\t"
        "mbarrier.try_wait.parity.acquire.cta.shared::cta.b64 p, [%1], %2;\n\t"
        "selp.b32 %0, 1, 0, p;\n\t}"
        : "=r"(done) : "r"(mbar), "r"(parity) : "memory");
    if (!done) {
        asm volatile(
            "{\n\t.reg .pred P1;\n\t"
            "WL_%=:\n\t"
            "mbarrier.try_wait.parity.acquire.cta.shared::cta.b64 P1, [%0], %1, 0x989680;\n\t"
            "@P1 bra.uni WD_%=;\n\t"
            "bra.uni WL_%=;\n\t"
            "WD_%=:\n\t}"
            :: "r"(mbar), "r"(parity) : "memory");
    }
}

__device__ __forceinline__ void issue_tile(int s, int ntiles, int bid,
                                           const float4* __restrict__ w,
                                           uint32_t smem_base, uint32_t mbar_base)
{
    if (s < ntiles) {
        const int      b  = s % 3;
        const uint32_t mb = mbar_base + 8u * b;
        asm volatile("mbarrier.arrive.expect_tx.shared.b64 _, [%0], %1;"
                     :: "r"(mb), "r"((uint32_t)TILE_B) : "memory");
        const void* src = (const void*)(w + (size_t)(bid + (s >> 2) * GRID) * NI
                                          + (size_t)(s & 3) * TILE_F4);
        asm volatile(
            "cp.async.bulk.shared::cluster.global.mbarrier::complete_tx::bytes "
            "[%0], [%1], %2, [%3];"
            :: "r"(smem_base + (uint32_t)OFF_RING + (uint32_t)(b * TILE_B)),
               "l"(src), "r"((uint32_t)TILE_B), "r"(mb) : "memory");
    }
}

__global__ __launch_bounds__(THREADS, 1)
void dvbundle_ring(const float4* __restrict__ w,
                   const float4* __restrict__ x,
                   const float*  __restrict__ v,
                   const float*  __restrict__ r,
                   float*        __restrict__ v_out,
                   float*        __restrict__ r_out,
                   float4*       __restrict__ w_out,
                   int n_neurons)
{
    extern __shared__ char smem[];
    float4* xs   = (float4*)(smem + OFF_X);
    float4* ring = (float4*)(smem + OFF_RING);
    float4* red  = (float4*)(smem + OFF_RED);

    const int tid  = threadIdx.x;
    const int warp = tid >> 5;
    const int lane = tid & 31;
    const int bid  = blockIdx.x;

    const uint32_t smem_base = (uint32_t)__cvta_generic_to_shared(smem);
    const uint32_t mbar_base = smem_base + OFF_MBAR;

    // ---- Prologue: x -> smem, init mbars, prime the ring ----
#pragma unroll
    for (int j = 0; j < 8; ++j)
        xs[tid + j * THREADS] = x[tid + j * THREADS];

    if (tid == 0) {
#pragma unroll
        for (int b = 0; b < NBUF; ++b)
            asm volatile("mbarrier.init.shared.b64 [%0], %1;"
                         :: "r"(mbar_base + 8u * b), "r"(1u) : "memory");
    }
    __syncthreads();

    const int niters = (n_neurons - bid + GRID - 1) / GRID;
    const int ntiles = 4 * niters;

    if (tid == 0) {
        issue_tile(0, ntiles, bid, w, smem_base, mbar_base);
        issue_tile(1, ntiles, bid, w, smem_base, mbar_base);
        issue_tile(2, ntiles, bid, w, smem_base, mbar_base);
    }

    int n = bid;
    for (int it = 0; it < niters; ++it, n += GRID) {
        const float vn = v[n];          // hoisted early, consumed post-reduce
        const float rn = r[n];

        float4 wv[8];
        float ax = 0.f, ay = 0.f, az = 0.f, aw = 0.f;
        const int s0 = 4 * it;

        // ---- Pass 1: 4 tiles, LDS -> regs -> FMA; refill each tile ----
#pragma unroll
        for (int q = 0; q < 4; ++q) {
            const int      s  = s0 + q;
            const int      b  = s % 3;
            const uint32_t ph = (uint32_t)(s / 3) & 1u;
            mbar_wait_parity(mbar_base + 8u * b, ph);

            const float4* wb = ring + b * TILE_F4;
            const float4 w0 = wb[tid];
            const float4 w1 = wb[tid + THREADS];
            const float4 x0 = xs[q * TILE_F4 + tid];
            const float4 x1 = xs[q * TILE_F4 + THREADS + tid];
            wv[2 * q]     = w0;
            wv[2 * q + 1] = w1;
            ax = fmaf(w0.x, x0.x, ax); ax = fmaf(w1.x, x1.x, ax);
            ay = fmaf(w0.y, x0.y, ay); ay = fmaf(w1.y, x1.y, ay);
            az = fmaf(w0.z, x0.z, az); az = fmaf(w1.z, x1.z, az);
            aw = fmaf(w0.w, x0.w, aw); aw = fmaf(w1.w, x1.w, aw);

            __syncthreads();                       // tile b fully consumed
            if (tid == 0)
                issue_tile(s + 3, ntiles, bid, w, smem_base, mbar_base);
        }

        // ---- Reduce: warp shfl -> smem partials -> 1 barrier ->
        //      every warp redundantly reduces all 32 partials ----
#pragma unroll
        for (int o = 16; o > 0; o >>= 1) {
            ax += __shfl_xor_sync(0xffffffffu, ax, o);
            ay += __shfl_xor_sync(0xffffffffu, ay, o);
            az += __shfl_xor_sync(0xffffffffu, az, o);
            aw += __shfl_xor_sync(0xffffffffu, aw, o);
        }
        if (lane == 0) red[warp] = make_float4(ax, ay, az, aw);
        __syncthreads();

        float4 t = red[lane];
        float Ix = t.x, Iy = t.y, Iz = t.z, Iw = t.w;
#pragma unroll
        for (int o = 16; o > 0; o >>= 1) {
            Ix += __shfl_xor_sync(0xffffffffu, Ix, o);
            Iy += __shfl_xor_sync(0xffffffffu, Iy, o);
            Iz += __shfl_xor_sync(0xffffffffu, Iz, o);
            Iw += __shfl_xor_sync(0xffffffffu, Iw, o);
        }

        // ---- Scalar neuron update ----
        const float S    = Ix - Iy + Iz - Iw;
        const float dv   = (S - vn) * 0.05f;            // DT/TAU_V
        const float th   = tanhf(vn);
        const float actd = (vn > 0.f) ? (1.f - th * th) : 0.f;
        const float reg  = rn * actd * dv * 0.02f;      // / TAU_W

        if (tid == 0) {
            v_out[n] = vn + dv;
            r_out[n] = (vn > 0.f) ? th : 0.f;
        }

        // ---- Pass 2: update from regs + smem x, direct STG ----
        float4* wdst = w_out + (size_t)n * NI;
#pragma unroll
        for (int q = 0; q < 4; ++q) {
#pragma unroll
            for (int h = 0; h < 2; ++h) {
                const int    idx = q * TILE_F4 + h * THREADS + tid;
                const float4 xv  = xs[idx];
                const float4 wj  = wv[2 * q + h];
                float4 o;
                o.x = fmaf(reg, fmaf(-wj.x, Ix, 0.5f * xv.x), wj.x);
                o.y = fmaf(reg, fmaf(-wj.y, Iy, 0.5f * xv.y), wj.y);
                o.z = fmaf(reg, fmaf(-wj.z, Iz, 0.5f * xv.z), wj.z);
                o.w = fmaf(reg, fmaf(-wj.w, Iw, 0.5f * xv.w), wj.w);
                wdst[idx] = o;
            }
        }
    }
}

extern "C" void kernel_launch(void* const* d_in, const int* in_sizes, int n_in,
                              void* d_out, int out_size)
{
    const float4* w = (const float4*)d_in[0];
    const float4* x = (const float4*)d_in[1];
    const float*  v = (const float*)d_in[2];
    const float*  r = (const float*)d_in[3];

    const int N = in_sizes[2];                 // 4096 neurons

    float*  out   = (float*)d_out;
    float*  v_out = out;
    float*  r_out = out + N;
    float4* w_out = (float4*)(out + 2 * (size_t)N);

    cudaFuncSetAttribute(dvbundle_ring,
                         cudaFuncAttributeMaxDynamicSharedMemorySize,
                         SMEM_B);

    dvbundle_ring<<<GRID, THREADS, SMEM_B>>>(w, x, v, r, v_out, r_out, w_out, N);
}